// round 11
// baseline (speedup 1.0000x reference)
#include <cuda_runtime.h>
#include <cuda_fp16.h>
#include <math.h>
#include <stdint.h>

#define BATCH 256
#define TT    1024
#define NT    512
#define RING  64
#define DSMEM 195584

// ---------------- static device state ----------------
__device__ __half g_h1r[RING][BATCH * 512];  // layer1 h ring (slot k+1 = h1[k]; slot0 zeros)
__device__ __half g_h2p[2][BATCH * 512];     // layer2 h ping-pong
__device__ __half g_w1p[2048 * 512];         // permuted Whh1, row p = hid*4+gate
__device__ __half g_w2p[2048 * 1024];        // permuted [Wih2 | Whh2] stacked in K
__device__ float  g_bs1p[2048];
__device__ float  g_bs2p[2048];
__device__ float  g_wih1p[2048];
__device__ float  g_xt[TT * BATCH];
__device__ unsigned g_c1h[2];                // L1 per-half step counters (32 arrivals/step)
__device__ unsigned g_c2h[2];                // L2 per-half step counters (32 arrivals/step)

__global__ void init_kernel(const float* __restrict__ x,
                            const float* __restrict__ Wih1,
                            const float* __restrict__ Whh1,
                            const float* __restrict__ bih1, const float* __restrict__ bhh1,
                            const float* __restrict__ Wih2,
                            const float* __restrict__ Whh2,
                            const float* __restrict__ bih2, const float* __restrict__ bhh2) {
    int i = blockIdx.x * blockDim.x + threadIdx.x;
    if (i < 2) { g_c1h[i] = 0u; g_c2h[i] = 0u; }
    if (i < 2048) {
        int orig = (i & 3) * 512 + (i >> 2);
        g_bs1p[i]  = bih1[orig] + bhh1[orig];
        g_bs2p[i]  = bih2[orig] + bhh2[orig];
        g_wih1p[i] = Wih1[orig];
    }
    if (i < 2048 * 512) {
        int p = i >> 9, c = i & 511;
        int orig = (p & 3) * 512 + (p >> 2);
        g_w1p[i] = __float2half_rn(Whh1[orig * 512 + c]);
    }
    if (i < 2048 * 1024) {
        int p = i >> 10, c = i & 1023;
        int orig = (p & 3) * 512 + (p >> 2);
        float v = (c < 512) ? Wih2[orig * 512 + c] : Whh2[orig * 512 + (c - 512)];
        g_w2p[i] = __float2half_rn(v);
    }
    if (i < BATCH * 512) g_h1r[0][i] = __float2half_rn(0.f);            // zero slot
    if (i < 2 * BATCH * 512) ((__half*)g_h2p)[i] = __float2half_rn(0.f);
    if (i < BATCH * TT) {
        int b = i >> 10, kk = i & 1023;
        g_xt[kk * BATCH + b] = x[i];
    }
}

// ---- MUFU activations ----
__device__ __forceinline__ float ex2f(float v) {
    float r; asm("ex2.approx.ftz.f32 %0, %1;" : "=f"(r) : "f"(v)); return r;
}
__device__ __forceinline__ float rcpf(float v) {
    float r; asm("rcp.approx.ftz.f32 %0, %1;" : "=f"(r) : "f"(v)); return r;
}
__device__ __forceinline__ float sigf(float v) {
    return rcpf(1.f + ex2f(v * -1.4426950408889634f));
}
__device__ __forceinline__ float tanhf_(float v) {
    return fmaf(-2.f, rcpf(ex2f(v * 2.8853900817779268f) + 1.f), 1.f);
}

// ---- async copy / ldmatrix / mma ----
__device__ __forceinline__ void cp_cg(uint32_t dst, const void* src) {
    asm volatile("cp.async.cg.shared.global [%0], [%1], 16;" :: "r"(dst), "l"(src));
}
__device__ __forceinline__ void cp_commit() { asm volatile("cp.async.commit_group;"); }
template<int N> __device__ __forceinline__ void cp_wait() {
    asm volatile("cp.async.wait_group %0;" :: "n"(N));
}
__device__ __forceinline__ void ldsm4(uint32_t& r0, uint32_t& r1, uint32_t& r2,
                                      uint32_t& r3, uint32_t addr) {
    asm volatile("ldmatrix.sync.aligned.m8n8.x4.shared.b16 {%0,%1,%2,%3}, [%4];"
                 : "=r"(r0), "=r"(r1), "=r"(r2), "=r"(r3) : "r"(addr));
}
__device__ __forceinline__ void mma16816(float* acc, uint32_t a0, uint32_t a1,
                                         uint32_t a2, uint32_t a3,
                                         uint32_t b0, uint32_t b1) {
    asm volatile(
        "mma.sync.aligned.m16n8k16.row.col.f32.f16.f16.f32 "
        "{%0,%1,%2,%3},{%4,%5,%6,%7},{%8,%9},{%0,%1,%2,%3};"
        : "+f"(acc[0]), "+f"(acc[1]), "+f"(acc[2]), "+f"(acc[3])
        : "r"(a0), "r"(a1), "r"(a2), "r"(a3), "r"(b0), "r"(b1));
}

__device__ __forceinline__ void spin_ge(unsigned* c, unsigned tgt) {
    volatile unsigned* p = c;
    while (*p < tgt) { __nanosleep(64); }
}

// ---------------- templated block body ----------------
// BR batch rows, GR gate rows, KT K depth, LAYER 0/1.
template<int BR, int GR, int KT, int LAYER>
__device__ __forceinline__ void run_block(char* dsm, int b0, int n0, int H,
                                          float* __restrict__ out) {
    constexpr int NCH  = KT / 64;
    constexpr int WST  = KT + 8;                          // W smem stride (halves)
    constexpr int SSBb = BR * 72 * 2;                     // one A stage, bytes
    constexpr int EXB  = BR * (GR + 4) * 4;               // exch bytes
    constexpr int REG  = (3 * SSBb > EXB) ? 3 * SSBb : EXB;
    constexpr int WOFb = REG;
    constexpr int COFb = WOFb + GR * WST * 2;
    constexpr int HL   = GR / 4;                          // hid units per block
    constexpr int EST  = GR + 4;                          // exch stride (floats)
    constexpr int WM   = BR / 32;

    float* exch = (float*)dsm;
    float* sc   = (float*)(dsm + COFb);
    const uint32_t sb0 = (uint32_t)__cvta_generic_to_shared(dsm);
    const uint32_t wb  = sb0 + WOFb;

    const int t = threadIdx.x;
    const int w = t >> 5, l = t & 31;
    const int wm = w % WM, wn = w / WM;
    const int m0 = wm * 32;
    const int n0w = wn * 16;
    const int arow = l & 15, acol8 = (l >> 4) * 8;

    // ---- one-time: weight tile into persistent smem; zero c ----
    {
        const __half* Wg = (LAYER == 0) ? (g_w1p + n0 * KT) : (g_w2p + n0 * KT);
        constexpr int SEGS = KT / 8;
#pragma unroll
        for (int i = 0; i < 16; i++) {
            int e = t + 512 * i;
            int r = e / SEGS, sg = e % SEGS;
            cp_cg(wb + (uint32_t)((r * WST + sg * 8) * 2), Wg + r * KT + sg * 8);
        }
        cp_commit(); cp_wait<0>();
        for (int i = t; i < BR * HL; i += NT) sc[i] = 0.f;
        __syncthreads();
    }

    for (int k = 0; k < TT; k++) {
        // ---- dataflow waits (top) ----
        if (t == 0) {
            if (LAYER == 0) {
                spin_ge(&g_c1h[H], (unsigned)(k * 32));              // own half step k-1 done
                if (k >= RING - 1)
                    spin_ge(&g_c2h[H], (unsigned)((k - (RING - 1)) * 32));  // ring reuse guard
            } else {
                spin_ge(&g_c1h[H], (unsigned)((k + 1) * 32));        // h1[k] ready
            }
        }
        __syncthreads();

        const __half* A1 = (LAYER == 0) ? (g_h1r[k & (RING - 1)] + b0 * 512)
                                        : (g_h1r[(k + 1) & (RING - 1)] + b0 * 512);
        const __half* A2 = g_h2p[(k & 1) ^ 1] + b0 * 512;            // L2 only

        // chunk source pointer
        auto srcp = [&](int cn) -> const __half* {
            return (LAYER == 1 && cn >= 8) ? (A2 + (cn - 8) * 64) : (A1 + cn * 64);
        };
        auto stld = [&](int st, const __half* cb) {
#pragma unroll
            for (int i = 0; i < BR * 8 / 512; i++) {
                int e = t + 512 * i, r = e >> 3, sg = e & 7;
                cp_cg(sb0 + (uint32_t)(st * SSBb + (r * 72 + sg * 8) * 2),
                      cb + r * 512 + sg * 8);
            }
        };

        float acc[2][2][4];
#pragma unroll
        for (int a = 0; a < 2; a++)
#pragma unroll
            for (int b = 0; b < 2; b++)
#pragma unroll
                for (int c = 0; c < 4; c++) acc[a][b][c] = 0.f;

        stld(0, srcp(0)); cp_commit();
        stld(1, srcp(1)); cp_commit();

#pragma unroll 1
        for (int ch = 0; ch < NCH; ch++) {
            cp_wait<1>();
            __syncthreads();
            if (LAYER == 1 && ch == 6) {           // before first h2-chunk load (cn=8)
                if (t == 0) spin_ge(&g_c2h[H], (unsigned)(k * 32));
                __syncthreads();
            }
            if (ch + 2 < NCH) stld((ch + 2) % 3, srcp(ch + 2));
            cp_commit();

            const uint32_t stg = sb0 + (uint32_t)((ch % 3) * SSBb);
#pragma unroll
            for (int ks = 0; ks < 4; ks++) {
                uint32_t a0, a1, a2, a3, a4, a5, a6, a7;
                ldsm4(a0, a1, a2, a3,
                      stg + (uint32_t)(((m0 + arow) * 72 + ks * 16 + acol8) * 2));
                ldsm4(a4, a5, a6, a7,
                      stg + (uint32_t)(((m0 + 16 + arow) * 72 + ks * 16 + acol8) * 2));
                const int kcol = ch * 64 + ks * 16 + acol8;
                uint32_t b0r, b1r, b2r, b3r;
                ldsm4(b0r, b1r, b2r, b3r,
                      wb + (uint32_t)(((n0w + arow) * WST + kcol) * 2));
                mma16816(acc[0][0], a0, a1, a2, a3, b0r, b2r);
                mma16816(acc[0][1], a0, a1, a2, a3, b1r, b3r);
                mma16816(acc[1][0], a4, a5, a6, a7, b0r, b2r);
                mma16816(acc[1][1], a4, a5, a6, a7, b1r, b3r);
            }
        }

        cp_wait<0>();
        __syncthreads();               // stages free; exch aliases them

        // epilogue -> exch
#pragma unroll
        for (int mf = 0; mf < 2; mf++)
#pragma unroll
            for (int ng = 0; ng < 2; ng++) {
                int row = m0 + mf * 16 + (l >> 2);
                int col = n0w + ng * 8 + 2 * (l & 3);
                *(float2*)(exch + row * EST + col) =
                    make_float2(acc[mf][ng][0], acc[mf][ng][1]);
                *(float2*)(exch + (row + 8) * EST + col) =
                    make_float2(acc[mf][ng][2], acc[mf][ng][3]);
            }
        __syncthreads();

        // ---- cell update ----
        __half* hw = (LAYER == 0) ? (g_h1r[(k + 1) & (RING - 1)])
                                  : (g_h2p[k & 1]);
#pragma unroll
        for (int j = 0; j < BR * HL / NT; j++) {
            int item = t + NT * j;
            int bl = item / HL, hl = item % HL;
            float4 v = *(float4*)(exch + bl * EST + hl * 4);
            float4 bs = *(const float4*)(((LAYER == 0) ? g_bs1p : g_bs2p) + n0 + hl * 4);
            float pi = v.x + bs.x, pf = v.y + bs.y, pg = v.z + bs.z, po = v.w + bs.w;
            if (LAYER == 0) {
                float xv = g_xt[k * BATCH + b0 + bl];
                float4 wv = *(const float4*)(g_wih1p + n0 + hl * 4);
                pi += xv * wv.x; pf += xv * wv.y; pg += xv * wv.z; po += xv * wv.w;
            }
            float i_ = sigf(pi), f_ = sigf(pf), g_ = tanhf_(pg), o_ = sigf(po);
            float c = fmaf(f_, sc[item], i_ * g_);
            sc[item] = c;
            float hv = o_ * tanhf_(c);
            hw[(b0 + bl) * 512 + (n0 >> 2) + hl] = __float2half_rn(hv);
            if (LAYER == 1 && k == TT - 1)
                out[(b0 + bl) * 512 + (n0 >> 2) + hl] = hv;
        }

        // ---- publish step ----
        __threadfence();
        __syncthreads();
        if (t == 0) atomicAdd((LAYER == 0) ? &g_c1h[H] : &g_c2h[H], 1u);
    }
}

__global__ __launch_bounds__(NT, 1)
void lstm_persist(float* __restrict__ out) {
    extern __shared__ __align__(16) char dsm[];
    const int bid = blockIdx.x;
    if (bid < 64) {                       // layer 1: 64b x 128g, K=512
        int b0 = (bid & 3) * 64, n0 = (bid >> 2) * 128;
        int H = (bid >> 1) & 1;
        run_block<64, 128, 512, 0>(dsm, b0, n0, H, out);
    } else {                              // layer 2: 128b x 64g, K=1024
        int id = bid - 64;
        int b0 = (id & 1) * 128, n0 = (id >> 1) * 64;
        int H = id & 1;
        run_block<128, 64, 1024, 1>(dsm, b0, n0, H, out);
    }
}

extern "C" void kernel_launch(void* const* d_in, const int* in_sizes, int n_in,
                              void* d_out, int out_size) {
    (void)in_sizes; (void)n_in; (void)out_size;
    const float* x    = (const float*)d_in[0];
    const float* Wih1 = (const float*)d_in[1];
    const float* Whh1 = (const float*)d_in[2];
    const float* bih1 = (const float*)d_in[3];
    const float* bhh1 = (const float*)d_in[4];
    const float* Wih2 = (const float*)d_in[5];
    const float* Whh2 = (const float*)d_in[6];
    const float* bih2 = (const float*)d_in[7];
    const float* bhh2 = (const float*)d_in[8];
    float* out = (float*)d_out;

    cudaFuncSetAttribute(lstm_persist, cudaFuncAttributeMaxDynamicSharedMemorySize, DSMEM);

    init_kernel<<<4096, 512>>>(x, Wih1, Whh1, bih1, bhh1, Wih2, Whh2, bih2, bhh2);
    lstm_persist<<<128, NT, DSMEM>>>(out);
}

// round 12
// speedup vs baseline: 1.1053x; 1.1053x over previous
#include <cuda_runtime.h>
#include <cuda_fp16.h>
#include <math.h>
#include <stdint.h>

#define BATCH 256
#define TT    1024
#define NBL   96
#define NT    512
#define SSBb  34816          /* one A stage: 128 rows x 136 halves x 2B */
#define DSMEM 202752         /* 2 stages + max W tile (128x520x2 = 133120) */

// ---------------- static device state ----------------
__device__ __half g_hc[2][BATCH * 1024];   // [buf][b][ h1(512) | h2(512) ]
__device__ __half g_w1p[2048 * 512];       // permuted Whh1, row p = hid*4+gate
__device__ __half g_w2p[2048 * 1024];      // permuted [Wih2 | Whh2] stacked in K
__device__ float  g_bs1p[2048];
__device__ float  g_bs2p[2048];
__device__ float  g_wih1p[2048];
__device__ float  g_xt[TT * BATCH];
__device__ unsigned g_cnt;

__global__ void init_kernel(const float* __restrict__ x,
                            const float* __restrict__ Wih1,
                            const float* __restrict__ Whh1,
                            const float* __restrict__ bih1, const float* __restrict__ bhh1,
                            const float* __restrict__ Wih2,
                            const float* __restrict__ Whh2,
                            const float* __restrict__ bih2, const float* __restrict__ bhh2) {
    int i = blockIdx.x * blockDim.x + threadIdx.x;
    if (i == 0) g_cnt = 0u;
    if (i < 2048) {
        int orig = (i & 3) * 512 + (i >> 2);
        g_bs1p[i]  = bih1[orig] + bhh1[orig];
        g_bs2p[i]  = bih2[orig] + bhh2[orig];
        g_wih1p[i] = Wih1[orig];
    }
    if (i < 2048 * 512) {
        int p = i >> 9, c = i & 511;
        int orig = (p & 3) * 512 + (p >> 2);
        g_w1p[i] = __float2half_rn(Whh1[orig * 512 + c]);
    }
    if (i < 2048 * 1024) {
        int p = i >> 10, c = i & 1023;
        int orig = (p & 3) * 512 + (p >> 2);
        float v = (c < 512) ? Wih2[orig * 512 + c] : Whh2[orig * 512 + (c - 512)];
        g_w2p[i] = __float2half_rn(v);
    }
    if (i < 2 * BATCH * 1024) ((__half*)g_hc)[i] = __float2half_rn(0.f);
    if (i < BATCH * TT) {
        int b = i >> 10, kk = i & 1023;
        g_xt[kk * BATCH + b] = x[i];
    }
}

// ---- MUFU activations ----
__device__ __forceinline__ float ex2f(float v) {
    float r; asm("ex2.approx.ftz.f32 %0, %1;" : "=f"(r) : "f"(v)); return r;
}
__device__ __forceinline__ float rcpf(float v) {
    float r; asm("rcp.approx.ftz.f32 %0, %1;" : "=f"(r) : "f"(v)); return r;
}
__device__ __forceinline__ float sigf(float v) {
    return rcpf(1.f + ex2f(v * -1.4426950408889634f));
}
__device__ __forceinline__ float tanhf_(float v) {
    return fmaf(-2.f, rcpf(ex2f(v * 2.8853900817779268f) + 1.f), 1.f);
}

// ---- async copy / ldmatrix / mma ----
__device__ __forceinline__ void cp_cg(uint32_t dst, const void* src) {
    asm volatile("cp.async.cg.shared.global [%0], [%1], 16;" :: "r"(dst), "l"(src));
}
__device__ __forceinline__ void cp_commit() { asm volatile("cp.async.commit_group;"); }
template<int N> __device__ __forceinline__ void cp_wait() {
    asm volatile("cp.async.wait_group %0;" :: "n"(N));
}
__device__ __forceinline__ void ldsm4(uint32_t& r0, uint32_t& r1, uint32_t& r2,
                                      uint32_t& r3, uint32_t addr) {
    asm volatile("ldmatrix.sync.aligned.m8n8.x4.shared.b16 {%0,%1,%2,%3}, [%4];"
                 : "=r"(r0), "=r"(r1), "=r"(r2), "=r"(r3) : "r"(addr));
}
__device__ __forceinline__ void mma16816(float* acc, uint32_t a0, uint32_t a1,
                                         uint32_t a2, uint32_t a3,
                                         uint32_t b0, uint32_t b1) {
    asm volatile(
        "mma.sync.aligned.m16n8k16.row.col.f32.f16.f16.f32 "
        "{%0,%1,%2,%3},{%4,%5,%6,%7},{%8,%9},{%0,%1,%2,%3};"
        : "+f"(acc[0]), "+f"(acc[1]), "+f"(acc[2]), "+f"(acc[3])
        : "r"(a0), "r"(a1), "r"(a2), "r"(a3), "r"(b0), "r"(b1));
}

__device__ __forceinline__ void gbar(unsigned target) {
    __threadfence();
    __syncthreads();
    if (threadIdx.x == 0) {
        atomicAdd(&g_cnt, 1u);
        volatile unsigned* p = &g_cnt;
        while (*p < target) { __nanosleep(32); }
    }
    __syncthreads();
}

// ---------------- templated block body ----------------
// Batch tile fixed 128 rows, Kc=128 chunks, 2-stage pipeline.
template<int GR, int KT, int LAYER>
__device__ __forceinline__ void run_block(char* dsm, int b0, int n0,
                                          float* __restrict__ out) {
    constexpr int NCH = KT / 128;
    constexpr int WST = KT + 8;            // W smem stride (halves)
    constexpr int NGF = GR / 32;           // n-frags per warp (4 or 2)
    constexpr int NGG = NGF / 2;           // shuffle groups

    const uint32_t sb0 = (uint32_t)__cvta_generic_to_shared(dsm);
    const uint32_t wb  = sb0 + 2 * SSBb;

    const int t = threadIdx.x;
    const int w = t >> 5, l = t & 31;
    const int wm = w & 3, wn = w >> 2;
    const int m0 = wm * 32;
    const int n0w = wn * (NGF * 8);
    const int arow = l & 15, acol8 = (l >> 4) * 8;
    const int q = l & 3, par = l & 1;

    // ---- one-time: weight tile into persistent smem ----
    {
        const __half* Wg = (LAYER == 0) ? (g_w1p + n0 * KT) : (g_w2p + n0 * KT);
#pragma unroll
        for (int i = 0; i < 16; i++) {
            int e = t + 512 * i;
            int r, sg;
            if (KT == 512) { r = e >> 6; sg = e & 63; }
            else           { r = e >> 7; sg = e & 127; }
            cp_cg(wb + (uint32_t)((r * WST + sg * 8) * 2), Wg + r * KT + sg * 8);
        }
        cp_commit(); cp_wait<0>();
        __syncthreads();
    }

    // cell state in registers
    float cc[2][NGG][2];
#pragma unroll
    for (int a = 0; a < 2; a++)
#pragma unroll
        for (int b = 0; b < NGG; b++) { cc[a][b][0] = 0.f; cc[a][b][1] = 0.f; }

    // per-lane hid indices (one per group)
    int hidg[NGG];
#pragma unroll
    for (int gg = 0; gg < NGG; gg++) {
        int hidw = 4 * gg + (par ? (2 + (q >> 1)) : (q >> 1));
        hidg[gg] = (n0 >> 2) + wn * (NGF * 2) + hidw;
    }

    unsigned bt = 0;

    for (int k = 0; k <= TT; k++) {
        const bool active = (LAYER == 0) ? (k < TT) : (k >= 1);
        if (active) {
            const __half* Ag = g_hc[(k - 1) & 1] + b0 * 1024;

            auto stld = [&](int st, int ch) {
                const __half* src = Ag + ch * 128;
#pragma unroll
                for (int i = 0; i < 4; i++) {
                    int e = t + 512 * i, r = e >> 4, sg = e & 15;
                    cp_cg(sb0 + (uint32_t)(st * SSBb + (r * 136 + sg * 8) * 2),
                          src + r * 1024 + sg * 8);
                }
            };

            float acc[2][NGF][4];
#pragma unroll
            for (int a = 0; a < 2; a++)
#pragma unroll
                for (int b = 0; b < NGF; b++)
#pragma unroll
                    for (int c = 0; c < 4; c++) acc[a][b][c] = 0.f;

            stld(0, 0); cp_commit();

#pragma unroll 1
            for (int ch = 0; ch < NCH; ch++) {
                cp_wait<0>();
                __syncthreads();
                if (ch + 1 < NCH) { stld((ch + 1) & 1, ch + 1); cp_commit(); }

                const uint32_t stg = sb0 + (uint32_t)((ch & 1) * SSBb);
#pragma unroll
                for (int ks = 0; ks < 8; ks++) {
                    uint32_t a0, a1, a2, a3, a4, a5, a6, a7;
                    ldsm4(a0, a1, a2, a3,
                          stg + (uint32_t)(((m0 + arow) * 136 + ks * 16 + acol8) * 2));
                    ldsm4(a4, a5, a6, a7,
                          stg + (uint32_t)(((m0 + 16 + arow) * 136 + ks * 16 + acol8) * 2));
                    const int kcol = ch * 128 + ks * 16 + acol8;
#pragma unroll
                    for (int bg = 0; bg < NGF / 2; bg++) {
                        uint32_t b0r, b1r, b2r, b3r;
                        ldsm4(b0r, b1r, b2r, b3r,
                              wb + (uint32_t)(((n0w + bg * 16 + arow) * WST + kcol) * 2));
                        mma16816(acc[0][bg * 2 + 0], a0, a1, a2, a3, b0r, b2r);
                        mma16816(acc[0][bg * 2 + 1], a0, a1, a2, a3, b1r, b3r);
                        mma16816(acc[1][bg * 2 + 0], a4, a5, a6, a7, b0r, b2r);
                        mma16816(acc[1][bg * 2 + 1], a4, a5, a6, a7, b1r, b3r);
                    }
                }
            }

            // ---- shuffle epilogue + in-register cell + direct h store ----
            __half* hcw = g_hc[k & 1];
            const int hoff = (LAYER == 0) ? 0 : 512;
#pragma unroll
            for (int mf = 0; mf < 2; mf++) {
#pragma unroll
                for (int gg = 0; gg < NGG; gg++) {
                    float4 bs = ((const float4*)((LAYER == 0) ? g_bs1p : g_bs2p))[hidg[gg]];
                    float4 wv;
                    if (LAYER == 0) wv = ((const float4*)g_wih1p)[hidg[gg]];
#pragma unroll
                    for (int rp = 0; rp < 2; rp++) {
                        float sa0 = acc[mf][2 * gg][rp * 2];
                        float sa1 = acc[mf][2 * gg][rp * 2 + 1];
                        float sb0f = acc[mf][2 * gg + 1][rp * 2];
                        float sb1f = acc[mf][2 * gg + 1][rp * 2 + 1];
                        float oa0 = __shfl_xor_sync(0xFFFFFFFFu, sa0, 1);
                        float oa1 = __shfl_xor_sync(0xFFFFFFFFu, sa1, 1);
                        float ob0 = __shfl_xor_sync(0xFFFFFFFFu, sb0f, 1);
                        float ob1 = __shfl_xor_sync(0xFFFFFFFFu, sb1f, 1);
                        float pi, pf, pg, po;
                        if (par == 0) { pi = sa0; pf = sa1; pg = oa0; po = oa1; }
                        else          { pi = ob0; pf = ob1; pg = sb0f; po = sb1f; }
                        pi += bs.x; pf += bs.y; pg += bs.z; po += bs.w;
                        int growM = b0 + m0 + mf * 16 + rp * 8 + (l >> 2);
                        if (LAYER == 0) {
                            float xv = g_xt[k * BATCH + growM];
                            pi += xv * wv.x; pf += xv * wv.y;
                            pg += xv * wv.z; po += xv * wv.w;
                        }
                        float i_ = sigf(pi), f_ = sigf(pf);
                        float g_ = tanhf_(pg), o_ = sigf(po);
                        float c = fmaf(f_, cc[mf][gg][rp], i_ * g_);
                        cc[mf][gg][rp] = c;
                        float hv = o_ * tanhf_(c);
                        hcw[growM * 1024 + hoff + hidg[gg]] = __float2half_rn(hv);
                        if (LAYER == 1 && k == TT)
                            out[growM * 512 + hidg[gg]] = hv;
                    }
                }
            }
        }

        bt += NBL;
        gbar(bt);
    }
}

__global__ __launch_bounds__(NT, 1)
void lstm_persist(float* __restrict__ out) {
    extern __shared__ __align__(16) char dsm[];
    const int bid = blockIdx.x;
    if (bid < 32) {                       // layer 1: 128b x 128g, K=512
        int b0 = (bid & 1) * 128, n0 = (bid >> 1) * 128;
        run_block<128, 512, 0>(dsm, b0, n0, out);
    } else {                              // layer 2: 128b x 64g, K=1024
        int id = bid - 32;
        int b0 = (id & 1) * 128, n0 = (id >> 1) * 64;
        run_block<64, 1024, 1>(dsm, b0, n0, out);
    }
}

extern "C" void kernel_launch(void* const* d_in, const int* in_sizes, int n_in,
                              void* d_out, int out_size) {
    (void)in_sizes; (void)n_in; (void)out_size;
    const float* x    = (const float*)d_in[0];
    const float* Wih1 = (const float*)d_in[1];
    const float* Whh1 = (const float*)d_in[2];
    const float* bih1 = (const float*)d_in[3];
    const float* bhh1 = (const float*)d_in[4];
    const float* Wih2 = (const float*)d_in[5];
    const float* Whh2 = (const float*)d_in[6];
    const float* bih2 = (const float*)d_in[7];
    const float* bhh2 = (const float*)d_in[8];
    float* out = (float*)d_out;

    cudaFuncSetAttribute(lstm_persist, cudaFuncAttributeMaxDynamicSharedMemorySize, DSMEM);

    init_kernel<<<4096, 512>>>(x, Wih1, Whh1, bih1, bhh1, Wih2, Whh2, bih2, bhh2);
    lstm_persist<<<NBL, NT, DSMEM>>>(out);
}

// round 13
// speedup vs baseline: 1.1200x; 1.0133x over previous
#include <cuda_runtime.h>
#include <cuda_fp16.h>
#include <math.h>
#include <stdint.h>

#define BATCH 256
#define TT    1024
#define NBL   96
#define GRPB  48             /* blocks per barrier group (one per batch half) */
#define NT    512
#define SSBb  34816          /* one A stage: 128 rows x 136 halves x 2B */
#define DSMEM 202752         /* 2 stages + max W tile (128x520x2 = 133120) */

// ---------------- static device state ----------------
__device__ __half g_hc[2][BATCH * 1024];   // [buf][b][ h1(512) | h2(512) ]
__device__ __half g_w1p[2048 * 512];       // permuted Whh1, row p = hid*4+gate
__device__ __half g_w2p[2048 * 1024];      // permuted [Wih2 | Whh2] stacked in K
__device__ float  g_bs1p[2048];
__device__ float  g_bs2p[2048];
__device__ float  g_wih1p[2048];
__device__ float  g_xt[TT * BATCH];
__device__ unsigned g_cnt2[2];             // per-half epoch counters

__global__ void init_kernel(const float* __restrict__ x,
                            const float* __restrict__ Wih1,
                            const float* __restrict__ Whh1,
                            const float* __restrict__ bih1, const float* __restrict__ bhh1,
                            const float* __restrict__ Wih2,
                            const float* __restrict__ Whh2,
                            const float* __restrict__ bih2, const float* __restrict__ bhh2) {
    int i = blockIdx.x * blockDim.x + threadIdx.x;
    if (i < 2) g_cnt2[i] = 0u;
    if (i < 2048) {
        int orig = (i & 3) * 512 + (i >> 2);
        g_bs1p[i]  = bih1[orig] + bhh1[orig];
        g_bs2p[i]  = bih2[orig] + bhh2[orig];
        g_wih1p[i] = Wih1[orig];
    }
    if (i < 2048 * 512) {
        int p = i >> 9, c = i & 511;
        int orig = (p & 3) * 512 + (p >> 2);
        g_w1p[i] = __float2half_rn(Whh1[orig * 512 + c]);
    }
    if (i < 2048 * 1024) {
        int p = i >> 10, c = i & 1023;
        int orig = (p & 3) * 512 + (p >> 2);
        float v = (c < 512) ? Wih2[orig * 512 + c] : Whh2[orig * 512 + (c - 512)];
        g_w2p[i] = __float2half_rn(v);
    }
    if (i < 2 * BATCH * 1024) ((__half*)g_hc)[i] = __float2half_rn(0.f);
    if (i < BATCH * TT) {
        int b = i >> 10, kk = i & 1023;
        g_xt[kk * BATCH + b] = x[i];
    }
}

// ---- MUFU activations ----
__device__ __forceinline__ float ex2f(float v) {
    float r; asm("ex2.approx.ftz.f32 %0, %1;" : "=f"(r) : "f"(v)); return r;
}
__device__ __forceinline__ float rcpf(float v) {
    float r; asm("rcp.approx.ftz.f32 %0, %1;" : "=f"(r) : "f"(v)); return r;
}
__device__ __forceinline__ float sigf(float v) {
    return rcpf(1.f + ex2f(v * -1.4426950408889634f));
}
__device__ __forceinline__ float tanhf_(float v) {
    return fmaf(-2.f, rcpf(ex2f(v * 2.8853900817779268f) + 1.f), 1.f);
}

// ---- async copy / ldmatrix / mma ----
__device__ __forceinline__ void cp_cg(uint32_t dst, const void* src) {
    asm volatile("cp.async.cg.shared.global [%0], [%1], 16;" :: "r"(dst), "l"(src));
}
__device__ __forceinline__ void cp_commit() { asm volatile("cp.async.commit_group;"); }
template<int N> __device__ __forceinline__ void cp_wait() {
    asm volatile("cp.async.wait_group %0;" :: "n"(N));
}
__device__ __forceinline__ void ldsm4(uint32_t& r0, uint32_t& r1, uint32_t& r2,
                                      uint32_t& r3, uint32_t addr) {
    asm volatile("ldmatrix.sync.aligned.m8n8.x4.shared.b16 {%0,%1,%2,%3}, [%4];"
                 : "=r"(r0), "=r"(r1), "=r"(r2), "=r"(r3) : "r"(addr));
}
__device__ __forceinline__ void mma16816(float* acc, uint32_t a0, uint32_t a1,
                                         uint32_t a2, uint32_t a3,
                                         uint32_t b0, uint32_t b1) {
    asm volatile(
        "mma.sync.aligned.m16n8k16.row.col.f32.f16.f16.f32 "
        "{%0,%1,%2,%3},{%4,%5,%6,%7},{%8,%9},{%0,%1,%2,%3};"
        : "+f"(acc[0]), "+f"(acc[1]), "+f"(acc[2]), "+f"(acc[3])
        : "r"(a0), "r"(a1), "r"(a2), "r"(a3), "r"(b0), "r"(b1));
}

// release-arrive / acquire-poll group barrier (no full fence, no sleep)
__device__ __forceinline__ void gbar(unsigned target, unsigned* cnt) {
    __syncthreads();
    if (threadIdx.x == 0) {
        asm volatile("red.release.gpu.global.add.u32 [%0], 1;" :: "l"(cnt) : "memory");
        unsigned v;
        do {
            asm volatile("ld.acquire.gpu.global.u32 %0, [%1];"
                         : "=r"(v) : "l"(cnt) : "memory");
        } while (v < target);
    }
    __syncthreads();
}

// ---------------- templated block body ----------------
// Batch tile fixed 128 rows, Kc=128 chunks, 2-stage pipeline.
template<int GR, int KT, int LAYER>
__device__ __forceinline__ void run_block(char* dsm, int b0, int n0,
                                          float* __restrict__ out) {
    constexpr int NCH = KT / 128;
    constexpr int WST = KT + 8;            // W smem stride (halves)
    constexpr int NGF = GR / 32;           // n-frags per warp (4 or 2)
    constexpr int NGG = NGF / 2;           // shuffle groups

    const uint32_t sb0 = (uint32_t)__cvta_generic_to_shared(dsm);
    const uint32_t wb  = sb0 + 2 * SSBb;

    const int t = threadIdx.x;
    const int w = t >> 5, l = t & 31;
    const int wm = w & 3, wn = w >> 2;
    const int m0 = wm * 32;
    const int n0w = wn * (NGF * 8);
    const int arow = l & 15, acol8 = (l >> 4) * 8;
    const int q = l & 3, par = l & 1;

    unsigned* cnt = &g_cnt2[(b0 >> 7) & 1];

    // ---- one-time: weight tile into persistent smem ----
    {
        const __half* Wg = (LAYER == 0) ? (g_w1p + n0 * KT) : (g_w2p + n0 * KT);
#pragma unroll
        for (int i = 0; i < 16; i++) {
            int e = t + 512 * i;
            int r, sg;
            if (KT == 512) { r = e >> 6; sg = e & 63; }
            else           { r = e >> 7; sg = e & 127; }
            cp_cg(wb + (uint32_t)((r * WST + sg * 8) * 2), Wg + r * KT + sg * 8);
        }
        cp_commit(); cp_wait<0>();
        __syncthreads();
    }

    // cell state in registers
    float cc[2][NGG][2];
#pragma unroll
    for (int a = 0; a < 2; a++)
#pragma unroll
        for (int b = 0; b < NGG; b++) { cc[a][b][0] = 0.f; cc[a][b][1] = 0.f; }

    // per-lane hid indices (one per group)
    int hidg[NGG];
#pragma unroll
    for (int gg = 0; gg < NGG; gg++) {
        int hidw = 4 * gg + (par ? (2 + (q >> 1)) : (q >> 1));
        hidg[gg] = (n0 >> 2) + wn * (NGF * 2) + hidw;
    }

    unsigned bt = 0;

    for (int k = 0; k <= TT; k++) {
        const bool active = (LAYER == 0) ? (k < TT) : (k >= 1);
        if (active) {
            const __half* Ag = g_hc[(k - 1) & 1] + b0 * 1024;

            auto stld = [&](int st, int ch) {
                const __half* src = Ag + ch * 128;
#pragma unroll
                for (int i = 0; i < 4; i++) {
                    int e = t + 512 * i, r = e >> 4, sg = e & 15;
                    cp_cg(sb0 + (uint32_t)(st * SSBb + (r * 136 + sg * 8) * 2),
                          src + r * 1024 + sg * 8);
                }
            };

            float acc[2][NGF][4];
#pragma unroll
            for (int a = 0; a < 2; a++)
#pragma unroll
                for (int b = 0; b < NGF; b++)
#pragma unroll
                    for (int c = 0; c < 4; c++) acc[a][b][c] = 0.f;

            stld(0, 0); cp_commit();

#pragma unroll 1
            for (int ch = 0; ch < NCH; ch++) {
                cp_wait<0>();
                __syncthreads();
                if (ch + 1 < NCH) { stld((ch + 1) & 1, ch + 1); cp_commit(); }

                const uint32_t stg = sb0 + (uint32_t)((ch & 1) * SSBb);
#pragma unroll
                for (int ks = 0; ks < 8; ks++) {
                    uint32_t a0, a1, a2, a3, a4, a5, a6, a7;
                    ldsm4(a0, a1, a2, a3,
                          stg + (uint32_t)(((m0 + arow) * 136 + ks * 16 + acol8) * 2));
                    ldsm4(a4, a5, a6, a7,
                          stg + (uint32_t)(((m0 + 16 + arow) * 136 + ks * 16 + acol8) * 2));
                    const int kcol = ch * 128 + ks * 16 + acol8;
#pragma unroll
                    for (int bg = 0; bg < NGF / 2; bg++) {
                        uint32_t b0r, b1r, b2r, b3r;
                        ldsm4(b0r, b1r, b2r, b3r,
                              wb + (uint32_t)(((n0w + bg * 16 + arow) * WST + kcol) * 2));
                        mma16816(acc[0][bg * 2 + 0], a0, a1, a2, a3, b0r, b2r);
                        mma16816(acc[0][bg * 2 + 1], a0, a1, a2, a3, b1r, b3r);
                        mma16816(acc[1][bg * 2 + 0], a4, a5, a6, a7, b0r, b2r);
                        mma16816(acc[1][bg * 2 + 1], a4, a5, a6, a7, b1r, b3r);
                    }
                }
            }

            // ---- shuffle epilogue + in-register cell + coalesced h store ----
            __half* hcw = g_hc[k & 1];
            const int hoff = (LAYER == 0) ? 0 : 512;
#pragma unroll
            for (int mf = 0; mf < 2; mf++) {
#pragma unroll
                for (int gg = 0; gg < NGG; gg++) {
                    float4 bs = ((const float4*)((LAYER == 0) ? g_bs1p : g_bs2p))[hidg[gg]];
                    float4 wv;
                    if (LAYER == 0) wv = ((const float4*)g_wih1p)[hidg[gg]];
#pragma unroll
                    for (int rp = 0; rp < 2; rp++) {
                        float sa0 = acc[mf][2 * gg][rp * 2];
                        float sa1 = acc[mf][2 * gg][rp * 2 + 1];
                        float sb0f = acc[mf][2 * gg + 1][rp * 2];
                        float sb1f = acc[mf][2 * gg + 1][rp * 2 + 1];
                        float oa0 = __shfl_xor_sync(0xFFFFFFFFu, sa0, 1);
                        float oa1 = __shfl_xor_sync(0xFFFFFFFFu, sa1, 1);
                        float ob0 = __shfl_xor_sync(0xFFFFFFFFu, sb0f, 1);
                        float ob1 = __shfl_xor_sync(0xFFFFFFFFu, sb1f, 1);
                        float pi, pf, pg, po;
                        if (par == 0) { pi = sa0; pf = sa1; pg = oa0; po = oa1; }
                        else          { pi = ob0; pf = ob1; pg = sb0f; po = sb1f; }
                        pi += bs.x; pf += bs.y; pg += bs.z; po += bs.w;
                        int growM = b0 + m0 + mf * 16 + rp * 8 + (l >> 2);
                        if (LAYER == 0) {
                            float xv = g_xt[k * BATCH + growM];
                            pi += xv * wv.x; pf += xv * wv.y;
                            pg += xv * wv.z; po += xv * wv.w;
                        }
                        float i_ = sigf(pi), f_ = sigf(pf);
                        float g_ = tanhf_(pg), o_ = sigf(po);
                        float c = fmaf(f_, cc[mf][gg][rp], i_ * g_);
                        cc[mf][gg][rp] = c;
                        float hv = o_ * tanhf_(c);
                        // pair adjacent hids (lanes l and l^2) -> one __half2 store
                        float hv_o = __shfl_xor_sync(0xFFFFFFFFu, hv, 2);
                        if ((l & 2) == 0) {
                            __half2 hp = __floats2half2_rn(hv, hv_o);
                            *(__half2*)(hcw + growM * 1024 + hoff + hidg[gg]) = hp;
                        }
                        if (LAYER == 1 && k == TT)
                            out[growM * 512 + hidg[gg]] = hv;
                    }
                }
            }
        }

        bt += GRPB;
        gbar(bt, cnt);
    }
}

__global__ __launch_bounds__(NT, 1)
void lstm_persist(float* __restrict__ out) {
    extern __shared__ __align__(16) char dsm[];
    const int bid = blockIdx.x;
    if (bid < 32) {                       // layer 1: 128b x 128g, K=512
        int b0 = (bid & 1) * 128, n0 = (bid >> 1) * 128;
        run_block<128, 512, 0>(dsm, b0, n0, out);
    } else {                              // layer 2: 128b x 64g, K=1024
        int id = bid - 32;
        int b0 = (id & 1) * 128, n0 = (id >> 1) * 64;
        run_block<64, 1024, 1>(dsm, b0, n0, out);
    }
}

extern "C" void kernel_launch(void* const* d_in, const int* in_sizes, int n_in,
                              void* d_out, int out_size) {
    (void)in_sizes; (void)n_in; (void)out_size;
    const float* x    = (const float*)d_in[0];
    const float* Wih1 = (const float*)d_in[1];
    const float* Whh1 = (const float*)d_in[2];
    const float* bih1 = (const float*)d_in[3];
    const float* bhh1 = (const float*)d_in[4];
    const float* Wih2 = (const float*)d_in[5];
    const float* Whh2 = (const float*)d_in[6];
    const float* bih2 = (const float*)d_in[7];
    const float* bhh2 = (const float*)d_in[8];
    float* out = (float*)d_out;

    cudaFuncSetAttribute(lstm_persist, cudaFuncAttributeMaxDynamicSharedMemorySize, DSMEM);

    init_kernel<<<4096, 512>>>(x, Wih1, Whh1, bih1, bhh1, Wih2, Whh2, bih2, bhh2);
    lstm_persist<<<NBL, NT, DSMEM>>>(out);
}

// round 14
// speedup vs baseline: 1.3621x; 1.2161x over previous
#include <cuda_runtime.h>
#include <cuda_fp16.h>
#include <math.h>
#include <stdint.h>

#define BATCH 256
#define TT    1024
#define NBL   96
#define GRPB  48             /* blocks per barrier group (one per batch half) */
#define NT    512
#define TILEB 32768          /* one 128x128-half chunk, bytes */
#define WOFF  65536          /* 2 stages */
#define MBOFF 198656         /* WOFF + max W tile 133120 */
#define DSMEM 198784

// ---------------- static device state ----------------
// h state, tile-major + swizzled: [buf][batch-half][col-block][128r x 128c halves]
__device__ __align__(1024) __half g_hc2[2][2][8][16384];
__device__ __half g_w1p[2048 * 512];       // permuted Whh1, row p = hid*4+gate
__device__ __half g_w2p[2048 * 1024];      // permuted [Wih2 | Whh2] stacked in K
__device__ float  g_bs1p[2048];
__device__ float  g_bs2p[2048];
__device__ float  g_wih1p[2048];
__device__ float  g_xt[TT * BATCH];
__device__ unsigned g_cnt2[2];             // per-half epoch counters

__global__ void init_kernel(const float* __restrict__ x,
                            const float* __restrict__ Wih1,
                            const float* __restrict__ Whh1,
                            const float* __restrict__ bih1, const float* __restrict__ bhh1,
                            const float* __restrict__ Wih2,
                            const float* __restrict__ Whh2,
                            const float* __restrict__ bih2, const float* __restrict__ bhh2) {
    int i = blockIdx.x * blockDim.x + threadIdx.x;
    if (i < 2) g_cnt2[i] = 0u;
    if (i < 2048) {
        int orig = (i & 3) * 512 + (i >> 2);
        g_bs1p[i]  = bih1[orig] + bhh1[orig];
        g_bs2p[i]  = bih2[orig] + bhh2[orig];
        g_wih1p[i] = Wih1[orig];
    }
    if (i < 2048 * 512) {
        int p = i >> 9, c = i & 511;
        int orig = (p & 3) * 512 + (p >> 2);
        g_w1p[i] = __float2half_rn(Whh1[orig * 512 + c]);
    }
    if (i < 2048 * 1024) {
        int p = i >> 10, c = i & 1023;
        int orig = (p & 3) * 512 + (p >> 2);
        float v = (c < 512) ? Wih2[orig * 512 + c] : Whh2[orig * 512 + (c - 512)];
        g_w2p[i] = __float2half_rn(v);
    }
    if (i < 2 * 2 * 8 * 16384) ((__half*)g_hc2)[i] = __float2half_rn(0.f);
    if (i < BATCH * TT) {
        int b = i >> 10, kk = i & 1023;
        g_xt[kk * BATCH + b] = x[i];
    }
}

// ---- MUFU activations ----
__device__ __forceinline__ float ex2f(float v) {
    float r; asm("ex2.approx.ftz.f32 %0, %1;" : "=f"(r) : "f"(v)); return r;
}
__device__ __forceinline__ float rcpf(float v) {
    float r; asm("rcp.approx.ftz.f32 %0, %1;" : "=f"(r) : "f"(v)); return r;
}
__device__ __forceinline__ float sigf(float v) {
    return rcpf(1.f + ex2f(v * -1.4426950408889634f));
}
__device__ __forceinline__ float tanhf_(float v) {
    return fmaf(-2.f, rcpf(ex2f(v * 2.8853900817779268f) + 1.f), 1.f);
}

// ---- PTX helpers ----
__device__ __forceinline__ void cp_cg(uint32_t dst, const void* src) {
    asm volatile("cp.async.cg.shared.global [%0], [%1], 16;" :: "r"(dst), "l"(src));
}
__device__ __forceinline__ void cp_commit() { asm volatile("cp.async.commit_group;"); }
template<int N> __device__ __forceinline__ void cp_wait() {
    asm volatile("cp.async.wait_group %0;" :: "n"(N));
}
__device__ __forceinline__ void ldsm4(uint32_t& r0, uint32_t& r1, uint32_t& r2,
                                      uint32_t& r3, uint32_t addr) {
    asm volatile("ldmatrix.sync.aligned.m8n8.x4.shared.b16 {%0,%1,%2,%3}, [%4];"
                 : "=r"(r0), "=r"(r1), "=r"(r2), "=r"(r3) : "r"(addr));
}
__device__ __forceinline__ void mma16816(float* acc, uint32_t a0, uint32_t a1,
                                         uint32_t a2, uint32_t a3,
                                         uint32_t b0, uint32_t b1) {
    asm volatile(
        "mma.sync.aligned.m16n8k16.row.col.f32.f16.f16.f32 "
        "{%0,%1,%2,%3},{%4,%5,%6,%7},{%8,%9},{%0,%1,%2,%3};"
        : "+f"(acc[0]), "+f"(acc[1]), "+f"(acc[2]), "+f"(acc[3])
        : "r"(a0), "r"(a1), "r"(a2), "r"(a3), "r"(b0), "r"(b1));
}
__device__ __forceinline__ void mbar_init(uint32_t a, uint32_t cnt) {
    asm volatile("mbarrier.init.shared.b64 [%0], %1;" :: "r"(a), "r"(cnt) : "memory");
}
__device__ __forceinline__ void bulk_ld(uint32_t dst, const void* src, uint32_t mb) {
    asm volatile("mbarrier.arrive.expect_tx.shared.b64 _, [%0], %1;"
                 :: "r"(mb), "r"((uint32_t)TILEB) : "memory");
    asm volatile("cp.async.bulk.shared::cluster.global.mbarrier::complete_tx::bytes "
                 "[%0], [%1], %2, [%3];"
                 :: "r"(dst), "l"(src), "r"((uint32_t)TILEB), "r"(mb) : "memory");
}
__device__ __forceinline__ void mbar_wait(uint32_t a, unsigned ph) {
    asm volatile(
        "{\n\t.reg .pred P;\n\t"
        "MW_%=:\n\t"
        "mbarrier.try_wait.parity.acquire.cta.shared::cta.b64 P, [%0], %1;\n\t"
        "@!P bra MW_%=;\n\t}"
        :: "r"(a), "r"(ph) : "memory");
}
__device__ __forceinline__ uint32_t swz(uint32_t b) { return b ^ ((b >> 4) & 0x70); }

// release-arrive / acquire-poll group barrier
__device__ __forceinline__ void gbar(unsigned target, unsigned* cnt) {
    __syncthreads();
    if (threadIdx.x == 0) {
        asm volatile("red.release.gpu.global.add.u32 [%0], 1;" :: "l"(cnt) : "memory");
        unsigned v;
        do {
            asm volatile("ld.acquire.gpu.global.u32 %0, [%1];"
                         : "=r"(v) : "l"(cnt) : "memory");
        } while (v < target);
    }
    __syncthreads();
}

// ---------------- templated block body ----------------
template<int GR, int KT, int LAYER>
__device__ __forceinline__ void run_block(char* dsm, int b0, int n0,
                                          float* __restrict__ out) {
    constexpr int NCH = KT / 128;
    constexpr int WST = KT + 8;
    constexpr int NGF = GR / 32;
    constexpr int NGG = NGF / 2;

    const uint32_t sb0 = (uint32_t)__cvta_generic_to_shared(dsm);
    const uint32_t wb  = sb0 + WOFF;
    const uint32_t mbar = sb0 + MBOFF;

    const int t = threadIdx.x;
    const int w = t >> 5, l = t & 31;
    const int wm = w & 3, wn = w >> 2;
    const int m0 = wm * 32;
    const int n0w = wn * (NGF * 8);
    const int arow = l & 15;
    const int acolb = (l >> 4) * 16;      // bytes
    const int q = l & 3, par = l & 1;
    const int hb = (b0 >> 7) & 1;

    unsigned* cnt = &g_cnt2[hb];

    if (t == 0) { mbar_init(mbar, 1); mbar_init(mbar + 8, 1); }

    // ---- one-time: weight tile into persistent smem ----
    {
        const __half* Wg = (LAYER == 0) ? (g_w1p + n0 * KT) : (g_w2p + n0 * KT);
#pragma unroll
        for (int i = 0; i < 16; i++) {
            int e = t + 512 * i;
            int r, sg;
            if (KT == 512) { r = e >> 6; sg = e & 63; }
            else           { r = e >> 7; sg = e & 127; }
            cp_cg(wb + (uint32_t)((r * WST + sg * 8) * 2), Wg + r * KT + sg * 8);
        }
        cp_commit(); cp_wait<0>();
        __syncthreads();
    }

    float cc[2][NGG][2];
#pragma unroll
    for (int a = 0; a < 2; a++)
#pragma unroll
        for (int b = 0; b < NGG; b++) { cc[a][b][0] = 0.f; cc[a][b][1] = 0.f; }

    int hidg[NGG];
#pragma unroll
    for (int gg = 0; gg < NGG; gg++) {
        int hidw = 4 * gg + (par ? (2 + (q >> 1)) : (q >> 1));
        hidg[gg] = (n0 >> 2) + wn * (NGF * 2) + hidw;
    }

    unsigned phs0 = 0, phs1 = 0;
    unsigned bt = 0;

    for (int k = 0; k <= TT; k++) {
        const bool active = (LAYER == 0) ? (k < TT) : (k >= 1);
        if (active) {
            const char* Ag = (const char*)&g_hc2[(k - 1) & 1][hb][0][0];

            float acc[2][NGF][4];
#pragma unroll
            for (int a = 0; a < 2; a++)
#pragma unroll
                for (int b = 0; b < NGF; b++)
#pragma unroll
                    for (int c = 0; c < 4; c++) acc[a][b][c] = 0.f;

            if (t == 0) {
                bulk_ld(sb0, Ag, mbar);
                bulk_ld(sb0 + TILEB, Ag + TILEB, mbar + 8);
            }

#pragma unroll 1
            for (int ch = 0; ch < NCH; ch++) {
                if (ch & 1) { mbar_wait(mbar + 8, phs1); phs1 ^= 1; }
                else        { mbar_wait(mbar, phs0); phs0 ^= 1; }

                const uint32_t stg = sb0 + (uint32_t)((ch & 1) * TILEB);
#pragma unroll
                for (int ks = 0; ks < 8; ks++) {
                    uint32_t ra0 = (uint32_t)((m0 + arow) * 256 + ks * 32 + acolb);
                    uint32_t ra1 = ra0 + 16 * 256;
                    uint32_t a0, a1, a2, a3, a4, a5, a6, a7;
                    ldsm4(a0, a1, a2, a3, stg + swz(ra0));
                    ldsm4(a4, a5, a6, a7, stg + swz(ra1));
                    const int kcol = ch * 128 + ks * 16 + acolb / 2;
#pragma unroll
                    for (int bg = 0; bg < NGF / 2; bg++) {
                        uint32_t b0r, b1r, b2r, b3r;
                        ldsm4(b0r, b1r, b2r, b3r,
                              wb + (uint32_t)(((n0w + bg * 16 + arow) * WST + kcol) * 2));
                        mma16816(acc[0][bg * 2 + 0], a0, a1, a2, a3, b0r, b2r);
                        mma16816(acc[0][bg * 2 + 1], a0, a1, a2, a3, b1r, b3r);
                        mma16816(acc[1][bg * 2 + 0], a4, a5, a6, a7, b0r, b2r);
                        mma16816(acc[1][bg * 2 + 1], a4, a5, a6, a7, b1r, b3r);
                    }
                }
                __syncthreads();         // all reads of this stage done
                if (ch + 2 < NCH && t == 0)
                    bulk_ld(sb0 + (uint32_t)((ch & 1) * TILEB),
                            Ag + (ch + 2) * TILEB,
                            mbar + (ch & 1) * 8);
            }

            // ---- shuffle epilogue + in-register cell + swizzled tile-major h store ----
            char* hcw = (char*)&g_hc2[k & 1][hb][0][0];
            const int hoff = (LAYER == 0) ? 0 : 512;
#pragma unroll
            for (int mf = 0; mf < 2; mf++) {
#pragma unroll
                for (int gg = 0; gg < NGG; gg++) {
                    float4 bs = ((const float4*)((LAYER == 0) ? g_bs1p : g_bs2p))[hidg[gg]];
                    float4 wv;
                    if (LAYER == 0) wv = ((const float4*)g_wih1p)[hidg[gg]];
#pragma unroll
                    for (int rp = 0; rp < 2; rp++) {
                        float sa0 = acc[mf][2 * gg][rp * 2];
                        float sa1 = acc[mf][2 * gg][rp * 2 + 1];
                        float sb0f = acc[mf][2 * gg + 1][rp * 2];
                        float sb1f = acc[mf][2 * gg + 1][rp * 2 + 1];
                        float oa0 = __shfl_xor_sync(0xFFFFFFFFu, sa0, 1);
                        float oa1 = __shfl_xor_sync(0xFFFFFFFFu, sa1, 1);
                        float ob0 = __shfl_xor_sync(0xFFFFFFFFu, sb0f, 1);
                        float ob1 = __shfl_xor_sync(0xFFFFFFFFu, sb1f, 1);
                        float pi, pf, pg, po;
                        if (par == 0) { pi = sa0; pf = sa1; pg = oa0; po = oa1; }
                        else          { pi = ob0; pf = ob1; pg = sb0f; po = sb1f; }
                        pi += bs.x; pf += bs.y; pg += bs.z; po += bs.w;
                        int growM = b0 + m0 + mf * 16 + rp * 8 + (l >> 2);
                        if (LAYER == 0) {
                            float xv = g_xt[k * BATCH + growM];
                            pi += xv * wv.x; pf += xv * wv.y;
                            pg += xv * wv.z; po += xv * wv.w;
                        }
                        float i_ = sigf(pi), f_ = sigf(pf);
                        float g_ = tanhf_(pg), o_ = sigf(po);
                        float c = fmaf(f_, cc[mf][gg][rp], i_ * g_);
                        cc[mf][gg][rp] = c;
                        float hv = o_ * tanhf_(c);
                        float hv_o = __shfl_xor_sync(0xFFFFFFFFu, hv, 2);
                        if ((l & 2) == 0) {
                            int col = hoff + hidg[gg];
                            uint32_t tb = (uint32_t)((growM & 127) * 256 + (col & 127) * 2);
                            tb = swz(tb);
                            __half2 hp = __floats2half2_rn(hv, hv_o);
                            *(__half2*)(hcw + (col >> 7) * TILEB + tb) = hp;
                        }
                        if (LAYER == 1 && k == TT)
                            out[growM * 512 + hidg[gg]] = hv;
                    }
                }
            }
        }

        bt += GRPB;
        gbar(bt, cnt);
    }
}

__global__ __launch_bounds__(NT, 1)
void lstm_persist(float* __restrict__ out) {
    extern __shared__ __align__(16) char dsm[];
    const int bid = blockIdx.x;
    if (bid < 32) {                       // layer 1: 128b x 128g, K=512
        int b0 = (bid & 1) * 128, n0 = (bid >> 1) * 128;
        run_block<128, 512, 0>(dsm, b0, n0, out);
    } else {                              // layer 2: 128b x 64g, K=1024
        int id = bid - 32;
        int b0 = (id & 1) * 128, n0 = (id >> 1) * 64;
        run_block<64, 1024, 1>(dsm, b0, n0, out);
    }
}

extern "C" void kernel_launch(void* const* d_in, const int* in_sizes, int n_in,
                              void* d_out, int out_size) {
    (void)in_sizes; (void)n_in; (void)out_size;
    const float* x    = (const float*)d_in[0];
    const float* Wih1 = (const float*)d_in[1];
    const float* Whh1 = (const float*)d_in[2];
    const float* bih1 = (const float*)d_in[3];
    const float* bhh1 = (const float*)d_in[4];
    const float* Wih2 = (const float*)d_in[5];
    const float* Whh2 = (const float*)d_in[6];
    const float* bih2 = (const float*)d_in[7];
    const float* bhh2 = (const float*)d_in[8];
    float* out = (float*)d_out;

    cudaFuncSetAttribute(lstm_persist, cudaFuncAttributeMaxDynamicSharedMemorySize, DSMEM);

    init_kernel<<<4096, 512>>>(x, Wih1, Whh1, bih1, bhh1, Wih2, Whh2, bih2, bhh2);
    lstm_persist<<<NBL, NT, DSMEM>>>(out);
}